// round 1
// baseline (speedup 1.0000x reference)
#include <cuda_runtime.h>
#include <math.h>

// ---------------- problem constants ----------------
#define NB     2
#define CINC   8
#define COUTC  8
#define NLAT   128
#define NLON   256
#define EMB    256
#define HID    512
#define NLAY   4
#define LMAXC  128
#define MMAXC  129
#define PSP    (NLAT*NLON)            // 32768 spatial
#define ROWS   (NB*EMB*NLAT)          // 65536 fft rows
#define SPECN  (NB*EMB*LMAXC*MMAXC)   // 8454144 spectral elems

// ---------------- scratch (static device allocations) ----------------
__device__ float g_h [(size_t)NB*EMB*PSP];
__device__ float g_t [(size_t)NB*HID*PSP];
__device__ float g_Are[SPECN], g_Aim[SPECN];
__device__ float g_Bre[SPECN], g_Bim[SPECN];
__device__ float g_wtT[(size_t)MMAXC*NLAT*LMAXC];                 // sht_wt transposed [m][k][l]
__device__ float g_wre[(size_t)NLAY*LMAXC*EMB*EMB];               // spec_w packed [lay][l][i][o]
__device__ float g_wim[(size_t)NLAY*LMAXC*EMB*EMB];
__device__ float g_dre[NLON*132], g_dim2[NLON*132];               // fwd DFT [n][m] (padded 132)
__device__ float g_idc[MMAXC*NLON], g_ids[MMAXC*NLON];            // inv DFT [m][n]

__device__ __forceinline__ float gelu_tanh(float x){
    float x3 = x*x*x;
    return 0.5f*x*(1.0f + tanhf(0.79788456080286535588f*(x + 0.044715f*x3)));
}

// ---------------- table init (runs every launch; deterministic) ----------------
__global__ void k_init_tables(){
    const double PI_D = 3.141592653589793238462643383279502884;
    int i = blockIdx.x*blockDim.x + threadIdx.x;
    if (i < NLON*MMAXC){
        int n = i / MMAXC, m = i % MMAXC;
        double ang = -2.0*PI_D*(double)((n*m)&255)/256.0;
        double sc  =  2.0*PI_D/256.0;                 // 2*pi * (1/N) forward norm
        g_dre [n*132+m] = (float)(cos(ang)*sc);
        g_dim2[n*132+m] = (float)(sin(ang)*sc);
    }
    if (i < MMAXC*NLON){
        int m = i / NLON, n = i % NLON;
        double ang = 2.0*PI_D*(double)((n*m)&255)/256.0;
        if (m==0 || m==128){                          // DC / Nyquist: counted once, imag ignored
            g_idc[i] = (float)cos(ang);
            g_ids[i] = 0.f;
        } else {
            g_idc[i] = (float)( 2.0*cos(ang));
            g_ids[i] = (float)(-2.0*sin(ang));
        }
    }
}

// transpose sht_wt [m][l][k] -> [m][k][l] so the Legendre-fwd inner loop is coalesced
__global__ void k_prep_wt(const float* __restrict__ sht_wt){
    int i = blockIdx.x*blockDim.x + threadIdx.x;
    if (i >= MMAXC*LMAXC*NLAT) return;
    int k = i % NLAT;
    int l = (i / NLAT) % LMAXC;
    int m = i / (NLAT*LMAXC);
    g_wtT[((size_t)m*NLAT + k)*LMAXC + l] = sht_wt[i];
}

// re-pack spec_w [lay][i][o][l][2] -> [lay][l][i][o] re/im so dhconv W loads are coalesced
__global__ void k_pack_w(const float* __restrict__ spec_w){
    size_t i = (size_t)blockIdx.x*blockDim.x + threadIdx.x;
    const size_t total = (size_t)NLAY*LMAXC*EMB*EMB;
    if (i >= total) return;
    int o   = (int)(i % EMB);
    int ii  = (int)((i/EMB) % EMB);
    int l   = (int)((i/((size_t)EMB*EMB)) % LMAXC);
    int lay = (int)( i/((size_t)EMB*EMB*LMAXC));
    size_t src = ((((size_t)lay*EMB + ii)*EMB + o)*LMAXC + l)*2;
    g_wre[i] = spec_w[src];
    g_wim[i] = spec_w[src+1];
}

// ---------------- generic tiled SGEMM: C[b,m,n] = sum_k A[m,k]*B[b,k,n] (+epilogue) ---------
// flags: 1 = gelu, 2 = add residual addp[b,m,n], 4 = add shared addp[m,n] (pos embed)
#define BM 64
#define BN 64
#define BKK 16
__global__ __launch_bounds__(256) void k_sgemm(
    const float* __restrict__ A, const float* __restrict__ Bmat,
    float* __restrict__ C, const float* __restrict__ bias,
    const float* __restrict__ addp, int M, int N, int K, int flags)
{
    int b  = blockIdx.z;
    const float* Bp = Bmat + (size_t)b*K*N;
    float* Cp       = C    + (size_t)b*M*N;
    int m0 = blockIdx.y*BM, n0 = blockIdx.x*BN;
    __shared__ float As[BKK][BM+1];
    __shared__ float Bs[BKK][BN];
    int tid = threadIdx.x;
    int tx = tid & 15, ty = tid >> 4;
    float acc[4][4];
    #pragma unroll
    for (int i=0;i<4;i++)
        #pragma unroll
        for (int j=0;j<4;j++) acc[i][j]=0.f;

    for (int k0=0;k0<K;k0+=BKK){
        #pragma unroll
        for (int q=0;q<4;q++){
            int idx = tid + q*256;
            int r = idx>>4, c = idx&15;
            int gm = m0+r, gk = k0+c;
            As[c][r] = (gm<M && gk<K) ? A[(size_t)gm*K+gk] : 0.f;
        }
        #pragma unroll
        for (int q=0;q<4;q++){
            int idx = tid + q*256;
            int r = idx>>6, c = idx&63;
            int gk = k0+r;
            Bs[r][c] = (gk<K) ? Bp[(size_t)gk*N + n0 + c] : 0.f;
        }
        __syncthreads();
        #pragma unroll
        for (int kk=0;kk<BKK;kk++){
            float aa[4];
            #pragma unroll
            for (int i=0;i<4;i++) aa[i] = As[kk][ty*4+i];
            float4 bv = *reinterpret_cast<const float4*>(&Bs[kk][tx*4]);
            float bb[4] = {bv.x, bv.y, bv.z, bv.w};
            #pragma unroll
            for (int i=0;i<4;i++)
                #pragma unroll
                for (int j=0;j<4;j++)
                    acc[i][j] += aa[i]*bb[j];
        }
        __syncthreads();
    }
    #pragma unroll
    for (int i=0;i<4;i++){
        int gm = m0 + ty*4 + i;
        if (gm >= M) continue;
        float bvl = bias[gm];
        #pragma unroll
        for (int j=0;j<4;j++){
            int gn = n0 + tx*4 + j;
            float v = acc[i][j] + bvl;
            if (flags & 1) v = gelu_tanh(v);
            if (flags & 2) v += addp[(size_t)b*M*N + (size_t)gm*N + gn];
            if (flags & 4) v += addp[(size_t)gm*N + gn];
            Cp[(size_t)gm*N + gn] = v;
        }
    }
}

// ---------------- forward rFFT as DFT matmul: 32 rows per block ----------------
#define FR 32
__global__ __launch_bounds__(160) void k_fft_fwd(const float* __restrict__ h,
                                                 float* __restrict__ xre, float* __restrict__ xim){
    __shared__ float sh[FR][NLON];
    int row0 = blockIdx.x * FR;
    int t = threadIdx.x;
    for (int i = t; i < FR*NLON; i += 160)
        sh[i>>8][i&255] = h[(size_t)row0*NLON + i];
    __syncthreads();
    if (t < MMAXC){
        float ar[FR], ai[FR];
        #pragma unroll
        for (int r=0;r<FR;r++){ ar[r]=0.f; ai[r]=0.f; }
        for (int n=0;n<NLON;n++){
            float cr = g_dre[n*132+t], ci = g_dim2[n*132+t];
            #pragma unroll
            for (int r=0;r<FR;r++){
                float v = sh[r][n];
                ar[r] += v*cr; ai[r] += v*ci;
            }
        }
        #pragma unroll
        for (int r=0;r<FR;r++){
            size_t idx = (size_t)(row0+r)*MMAXC + t;
            xre[idx]=ar[r]; xim[idx]=ai[r];
        }
    }
}

// ---------------- inverse rFFT + gelu + residual (in-place into g_h) ----------------
#define IR 32
__global__ __launch_bounds__(256) void k_fft_inv(const float* __restrict__ yre,
                                                 const float* __restrict__ yim,
                                                 float* __restrict__ h){
    __shared__ float2 sv[IR][MMAXC];
    int row0 = blockIdx.x * IR;
    int t = threadIdx.x;
    for (int i = t; i < IR*MMAXC; i += 256){
        int r = i / MMAXC, m = i - r*MMAXC;
        size_t idx = (size_t)(row0+r)*MMAXC + m;
        sv[r][m] = make_float2(yre[idx], yim[idx]);
    }
    __syncthreads();
    float acc[IR];
    #pragma unroll
    for (int r=0;r<IR;r++) acc[r]=0.f;
    for (int m=0;m<MMAXC;m++){
        float c = g_idc[m*NLON+t], s = g_ids[m*NLON+t];
        #pragma unroll
        for (int r=0;r<IR;r++){
            float2 v = sv[r][m];
            acc[r] += v.x*c + v.y*s;
        }
    }
    #pragma unroll
    for (int r=0;r<IR;r++){
        size_t idx = (size_t)(row0+r)*NLON + t;
        h[idx] = gelu_tanh(acc[r]) + h[idx];   // residual: same index read/write per thread
    }
}

// ---------------- Legendre forward: hs[bc,l,m] = sum_k wt[m,l,k]*xf[bc,k,m] ----------------
__global__ __launch_bounds__(128) void k_leg_fwd(const float* __restrict__ xre,
                                                 const float* __restrict__ xim,
                                                 float* __restrict__ hre,
                                                 float* __restrict__ him){
    int bc0 = blockIdx.x * 8;
    int m   = blockIdx.y;
    int l   = threadIdx.x;
    __shared__ float2 s[8][NLAT];
    for (int i = l; i < 8*NLAT; i += 128){
        int r = i >> 7, k = i & 127;
        size_t idx = ((size_t)(bc0+r)*NLAT + k)*MMAXC + m;
        s[r][k] = make_float2(xre[idx], xim[idx]);
    }
    __syncthreads();
    float ar[8], ai[8];
    #pragma unroll
    for (int r=0;r<8;r++){ ar[r]=0.f; ai[r]=0.f; }
    const float* w = g_wtT + (size_t)m*NLAT*LMAXC;     // [k][l]
    for (int k=0;k<NLAT;k++){
        float wv = w[k*LMAXC + l];
        #pragma unroll
        for (int r=0;r<8;r++){
            float2 v = s[r][k];
            ar[r] += wv*v.x; ai[r] += wv*v.y;
        }
    }
    #pragma unroll
    for (int r=0;r<8;r++){
        size_t idx = ((size_t)(bc0+r)*LMAXC + l)*MMAXC + m;
        hre[idx]=ar[r]; him[idx]=ai[r];
    }
}

// ---------------- Legendre inverse: y[bc,k,m] = sum_l wt[m,l,k]*hs[bc,l,m] ----------------
__global__ __launch_bounds__(128) void k_leg_inv(const float* __restrict__ hre,
                                                 const float* __restrict__ him,
                                                 float* __restrict__ yre,
                                                 float* __restrict__ yim,
                                                 const float* __restrict__ wt){
    int bc0 = blockIdx.x * 8;
    int m   = blockIdx.y;
    int k   = threadIdx.x;
    __shared__ float2 s[8][LMAXC];
    for (int i = k; i < 8*LMAXC; i += 128){
        int r = i >> 7, l = i & 127;
        size_t idx = ((size_t)(bc0+r)*LMAXC + l)*MMAXC + m;
        s[r][l] = make_float2(hre[idx], him[idx]);
    }
    __syncthreads();
    float ar[8], ai[8];
    #pragma unroll
    for (int r=0;r<8;r++){ ar[r]=0.f; ai[r]=0.f; }
    const float* w = wt + (size_t)m*LMAXC*NLAT;        // isht_wt [m][l][k] : coalesced over k
    for (int l=0;l<LMAXC;l++){
        float wv = w[l*NLAT + k];
        #pragma unroll
        for (int r=0;r<8;r++){
            float2 v = s[r][l];
            ar[r] += wv*v.x; ai[r] += wv*v.y;
        }
    }
    #pragma unroll
    for (int r=0;r<8;r++){
        size_t idx = ((size_t)(bc0+r)*NLAT + k)*MMAXC + m;
        yre[idx]=ar[r]; yim[idx]=ai[r];
    }
}

// ---------------- dhconv: out[b,o,l,m] = sum_i hs[b,i,l,m] * W[l][i][o] (complex) --------
__global__ __launch_bounds__(256) void k_dhconv(const float* __restrict__ hre,
                                                const float* __restrict__ him,
                                                float* __restrict__ ore,
                                                float* __restrict__ oim,
                                                const float* __restrict__ wre,
                                                const float* __restrict__ wim){
    int m0 = blockIdx.x * 32;
    int l  = blockIdx.y;
    int b  = blockIdx.z >> 2;
    int o0 = (blockIdx.z & 3) * 64;
    __shared__ float2 Av[16][33];
    __shared__ float2 Wv[16][64];
    int t  = threadIdx.x;
    int mm = t & 31, og = t >> 5;
    int m  = m0 + mm;
    bool mok = (m < MMAXC);
    float cre[8], cim[8];
    #pragma unroll
    for (int j=0;j<8;j++){ cre[j]=0.f; cim[j]=0.f; }
    const float* wrb = wre + (size_t)l*EMB*EMB;
    const float* wib = wim + (size_t)l*EMB*EMB;
    for (int i0=0;i0<EMB;i0+=16){
        {   // A tile: 16 i x 32 m
            int ii = t >> 5;
            #pragma unroll
            for (int p=0;p<2;p++){
                int iL = ii + p*8;
                size_t idx = ((size_t)(b*EMB + i0+iL)*LMAXC + l)*MMAXC + m;
                Av[iL][mm] = mok ? make_float2(hre[idx], him[idx]) : make_float2(0.f,0.f);
            }
        }
        {   // W tile: 16 i x 64 o (coalesced over o)
            int oo = t & 63, i4 = t >> 6;
            #pragma unroll
            for (int p=0;p<4;p++){
                int iL = i4 + p*4;
                size_t idx = (size_t)(i0+iL)*EMB + o0 + oo;
                Wv[iL][oo] = make_float2(wrb[idx], wib[idx]);
            }
        }
        __syncthreads();
        #pragma unroll
        for (int ii=0;ii<16;ii++){
            float2 a = Av[ii][mm];
            #pragma unroll
            for (int j=0;j<8;j++){
                float2 w = Wv[ii][og*8+j];
                cre[j] += a.x*w.x - a.y*w.y;
                cim[j] += a.x*w.y + a.y*w.x;
            }
        }
        __syncthreads();
    }
    if (mok){
        #pragma unroll
        for (int j=0;j<8;j++){
            int o = o0 + og*8 + j;
            size_t idx = ((size_t)(b*EMB + o)*LMAXC + l)*MMAXC + m;
            ore[idx]=cre[j]; oim[idx]=cim[j];
        }
    }
}

// ---------------- launcher ----------------
extern "C" void kernel_launch(void* const* d_in, const int* in_sizes, int n_in,
                              void* d_out, int out_size){
    const float* x       = (const float*)d_in[0];
    const float* w_enc   = (const float*)d_in[1];
    const float* b_enc   = (const float*)d_in[2];
    const float* pos     = (const float*)d_in[3];
    const float* spec_w  = (const float*)d_in[4];
    const float* w1      = (const float*)d_in[5];
    const float* b1      = (const float*)d_in[6];
    const float* w2      = (const float*)d_in[7];
    const float* b2      = (const float*)d_in[8];
    const float* w_dec   = (const float*)d_in[9];
    const float* b_dec   = (const float*)d_in[10];
    const float* sht_wt  = (const float*)d_in[11];
    const float* isht_wt = (const float*)d_in[12];
    float* out = (float*)d_out;

    float *ph, *pt, *pAre, *pAim, *pBre, *pBim, *pwre, *pwim;
    cudaGetSymbolAddress((void**)&ph,   g_h);
    cudaGetSymbolAddress((void**)&pt,   g_t);
    cudaGetSymbolAddress((void**)&pAre, g_Are);
    cudaGetSymbolAddress((void**)&pAim, g_Aim);
    cudaGetSymbolAddress((void**)&pBre, g_Bre);
    cudaGetSymbolAddress((void**)&pBim, g_Bim);
    cudaGetSymbolAddress((void**)&pwre, g_wre);
    cudaGetSymbolAddress((void**)&pwim, g_wim);

    // precompute tables / transposes / packs (deterministic each launch)
    k_init_tables<<<(NLON*MMAXC + 255)/256, 256>>>();
    k_prep_wt<<<(MMAXC*LMAXC*NLAT + 255)/256, 256>>>(sht_wt);
    {
        size_t tot = (size_t)NLAY*LMAXC*EMB*EMB;
        k_pack_w<<<(unsigned)((tot + 255)/256), 256>>>(spec_w);
    }

    // encoder: h = W_enc x + b_enc + pos
    {
        dim3 g(PSP/BN, (EMB+BM-1)/BM, NB);
        k_sgemm<<<g, 256>>>(w_enc, x, ph, b_enc, pos, EMB, PSP, CINC, 4);
    }

    for (int l=0;l<NLAY;l++){
        k_fft_fwd<<<ROWS/FR, 160>>>(ph, pAre, pAim);
        {
            dim3 g(NB*EMB/8, MMAXC);
            k_leg_fwd<<<g, 128>>>(pAre, pAim, pBre, pBim);
        }
        {
            dim3 g(5, LMAXC, NB*4);   // 5 m-tiles of 32 cover mmax=129
            k_dhconv<<<g, 256>>>(pBre, pBim, pAre, pAim,
                                 pwre + (size_t)l*LMAXC*EMB*EMB,
                                 pwim + (size_t)l*LMAXC*EMB*EMB);
        }
        {
            dim3 g(NB*EMB/8, MMAXC);
            k_leg_inv<<<g, 128>>>(pAre, pAim, pBre, pBim, isht_wt);
        }
        k_fft_inv<<<ROWS/IR, 256>>>(pBre, pBim, ph);   // + gelu + residual, in place

        {   // MLP1: t = gelu(W1 h + b1)
            dim3 g(PSP/BN, HID/BM, NB);
            k_sgemm<<<g, 256>>>(w1 + (size_t)l*HID*EMB, ph, pt,
                                b1 + (size_t)l*HID, nullptr, HID, PSP, EMB, 1);
        }
        {   // MLP2: h = W2 t + b2 + h
            dim3 g(PSP/BN, EMB/BM, NB);
            k_sgemm<<<g, 256>>>(w2 + (size_t)l*EMB*HID, pt, ph,
                                b2 + (size_t)l*EMB, ph, EMB, PSP, HID, 2);
        }
    }

    // decoder
    {
        dim3 g(PSP/BN, 1, NB);
        k_sgemm<<<g, 256>>>(w_dec, ph, out, b_dec, nullptr, COUTC, PSP, EMB, 0);
    }
}

// round 2
// speedup vs baseline: 1.0923x; 1.0923x over previous
#include <cuda_runtime.h>
#include <math.h>

typedef unsigned long long u64;

// ---------------- problem constants ----------------
#define NB     2
#define CINC   8
#define COUTC  8
#define NLAT   128
#define NLON   256
#define EMB    256
#define HID    512
#define NLAY   4
#define MM     129
#define MP     132                      // padded mmax (multiple of 4)
#define PSP    (NLAT*NLON)              // 32768
#define ROWS   (NB*EMB*NLAT)            // 65536

// ---------------- scratch ----------------
__device__ float2 g_A[(size_t)NB*EMB*NLAT*MP];     // spectral buf A  [bc][k|l][m132]
__device__ float2 g_B[(size_t)NB*EMB*NLAT*MP];     // spectral buf B
__device__ float  g_h [(size_t)NB*EMB*PSP];
__device__ float  g_t [(size_t)NB*HID*PSP];
__device__ float  g_wtT[(size_t)MP*NLAT*NLAT];     // sht_wt  -> [m][k][l], zero-padded m
__device__ float  g_iwt[(size_t)MP*NLAT*NLAT];     // isht_wt -> [m][l][k], zero-padded m
__device__ float2 g_w[(size_t)NLAY*NLAT*EMB*EMB];  // spec_w  -> [lay][l][i][o] complex
__device__ float2 g_dft[MP*NLON];                  // fwd DFT [m][n] (cr,ci)*2pi/256
__device__ float2 g_idt[MP*NLON];                  // inv DFT [m][n] (c, s)

// ---------------- f32x2 helpers ----------------
__device__ __forceinline__ u64 pk2(float lo, float hi){
    u64 r; asm("mov.b64 %0,{%1,%2};" : "=l"(r) : "f"(lo), "f"(hi)); return r;
}
__device__ __forceinline__ u64 dup2f(float v){ return pk2(v, v); }
__device__ __forceinline__ void fma2(u64 &d, u64 a, u64 b){
    asm("fma.rn.f32x2 %0,%1,%2,%0;" : "+l"(d) : "l"(a), "l"(b));
}
__device__ __forceinline__ float2 up2(u64 v){
    float x, y; asm("mov.b64 {%0,%1},%2;" : "=f"(x), "=f"(y) : "l"(v));
    return make_float2(x, y);
}
__device__ __forceinline__ float gelu_tanh(float x){
    float x3 = x*x*x;
    return 0.5f*x*(1.0f + tanhf(0.79788456080286535588f*(x + 0.044715f*x3)));
}

// ---------------- tables ----------------
__global__ void k_init_tables(){
    int i = blockIdx.x*blockDim.x + threadIdx.x;
    if (i >= MP*NLON) return;
    int m = i / NLON, n = i % NLON;
    const double PI_D = 3.141592653589793238462643383279502884;
    if (m < MM){
        double ang = -2.0*PI_D*(double)((n*m)&255)/256.0;
        double sc  =  2.0*PI_D/256.0;
        g_dft[i] = make_float2((float)(cos(ang)*sc), (float)(sin(ang)*sc));
        double a2 = 2.0*PI_D*(double)((n*m)&255)/256.0;
        if (m==0 || m==128)
            g_idt[i] = make_float2((float)cos(a2), 0.f);
        else
            g_idt[i] = make_float2((float)(2.0*cos(a2)), (float)(-2.0*sin(a2)));
    } else {
        g_dft[i] = make_float2(0.f,0.f);
        g_idt[i] = make_float2(0.f,0.f);
    }
}

// sht_wt[m][l][k] -> g_wtT[m][k][l] ; isht_wt[m][l][k] -> g_iwt[m][l][k]; pad m to 132 w/ zeros
__global__ void k_prep_wt(const float* __restrict__ sht, const float* __restrict__ isht){
    int i = blockIdx.x*blockDim.x + threadIdx.x;
    if (i >= MP*NLAT*NLAT) return;
    int t = i & 127;
    int j = (i >> 7) & 127;
    int m = i >> 14;
    float v1 = 0.f, v2 = 0.f;
    if (m < MM){
        v1 = sht [((size_t)m*NLAT + t)*NLAT + j];   // [m][l=t][k=j] -> out[m][k=j][l=t]
        v2 = isht[((size_t)m*NLAT + j)*NLAT + t];   // [m][l=j][k=t] -> out[m][l=j][k=t]
    }
    g_wtT[i] = v1;
    g_iwt[i] = v2;
}

// spec_w [lay][i][o][l]{re,im} -> g_w [lay][l][i][o] float2 (smem-tiled transpose)
__global__ __launch_bounds__(256) void k_pack_w(const float2* __restrict__ sw){
    __shared__ float2 tile[32][33];
    int li = blockIdx.x;                 // lay*256 + i
    int o0 = blockIdx.y*32, l0 = blockIdx.z*32;
    int oo = threadIdx.x >> 5, ll = threadIdx.x & 31;
    #pragma unroll
    for (int p=0;p<4;p++){
        int o = oo + p*8;
        tile[o][ll] = sw[((size_t)li*EMB + o0 + o)*NLAT + l0 + ll];
    }
    __syncthreads();
    int lay = li >> 8, ii = li & 255;
    #pragma unroll
    for (int p=0;p<4;p++){
        int l = oo + p*8;
        g_w[(((size_t)lay*NLAT + l0 + l)*EMB + ii)*EMB + o0 + ll] = tile[ll][l];
    }
}

// ---------------- SGEMM: C[b,m,n] = sum_k A[m,k]*B[b,k,n]  (128x128 tile, FFMA2) --------
// flags: 1 = gelu, 2 = add addp[b,m,n], 4 = add addp[m,n]
__global__ __launch_bounds__(256) void k_sgemm(
    const float* __restrict__ A, const float* __restrict__ Bmat,
    float* C, const float* bias, const float* addp,
    int M, int N, int K, int flags)
{
    __shared__ u64   Asd[8][128];
    __shared__ float Bs [8][128];
    int b = blockIdx.z;
    const float* Bp = Bmat + (size_t)b*K*N;
    float* Cp       = C    + (size_t)b*M*N;
    int m0 = blockIdx.y*128, n0 = blockIdx.x*128;
    int tid = threadIdx.x, tx = tid & 15, ty = tid >> 4;
    int ar = tid >> 1,  ac = (tid & 1)*4;
    int br = tid >> 5,  bc = (tid & 31)*4;
    u64 acc[8][4];
    #pragma unroll
    for (int i=0;i<8;i++)
        #pragma unroll
        for (int j=0;j<4;j++) acc[i][j]=0ull;

    for (int k0=0;k0<K;k0+=8){
        float4 av = make_float4(0.f,0.f,0.f,0.f);
        if (m0+ar < M) av = *(const float4*)&A[(size_t)(m0+ar)*K + k0 + ac];
        Asd[ac+0][ar]=dup2f(av.x); Asd[ac+1][ar]=dup2f(av.y);
        Asd[ac+2][ar]=dup2f(av.z); Asd[ac+3][ar]=dup2f(av.w);
        *(float4*)&Bs[br][bc] = *(const float4*)&Bp[(size_t)(k0+br)*N + n0 + bc];
        __syncthreads();
        #pragma unroll
        for (int kk=0;kk<8;kk++){
            ulonglong2 a01 = *(ulonglong2*)&Asd[kk][ty*8+0];
            ulonglong2 a23 = *(ulonglong2*)&Asd[kk][ty*8+2];
            ulonglong2 a45 = *(ulonglong2*)&Asd[kk][ty*8+4];
            ulonglong2 a67 = *(ulonglong2*)&Asd[kk][ty*8+6];
            float4 b03 = *(float4*)&Bs[kk][tx*8];
            float4 b47 = *(float4*)&Bs[kk][tx*8+4];
            u64 bb[4] = {pk2(b03.x,b03.y), pk2(b03.z,b03.w),
                         pk2(b47.x,b47.y), pk2(b47.z,b47.w)};
            u64 ad[8] = {a01.x,a01.y,a23.x,a23.y,a45.x,a45.y,a67.x,a67.y};
            #pragma unroll
            for (int i=0;i<8;i++)
                #pragma unroll
                for (int j=0;j<4;j++)
                    fma2(acc[i][j], ad[i], bb[j]);
        }
        __syncthreads();
    }
    #pragma unroll
    for (int i=0;i<8;i++){
        int gm = m0 + ty*8 + i;
        if (gm >= M) continue;
        float bvl = bias[gm];
        float r[8];
        #pragma unroll
        for (int j=0;j<4;j++){
            float2 c = up2(acc[i][j]);
            r[2*j]   = c.x + bvl;
            r[2*j+1] = c.y + bvl;
        }
        if (flags & 1){
            #pragma unroll
            for (int j=0;j<8;j++) r[j] = gelu_tanh(r[j]);
        }
        size_t off = (size_t)gm*N + n0 + tx*8;
        if (flags & 2){
            float4 p0 = *(const float4*)&addp[(size_t)b*M*N + off];
            float4 p1 = *(const float4*)&addp[(size_t)b*M*N + off + 4];
            r[0]+=p0.x; r[1]+=p0.y; r[2]+=p0.z; r[3]+=p0.w;
            r[4]+=p1.x; r[5]+=p1.y; r[6]+=p1.z; r[7]+=p1.w;
        }
        if (flags & 4){
            float4 p0 = *(const float4*)&addp[off];
            float4 p1 = *(const float4*)&addp[off + 4];
            r[0]+=p0.x; r[1]+=p0.y; r[2]+=p0.z; r[3]+=p0.w;
            r[4]+=p1.x; r[5]+=p1.y; r[6]+=p1.z; r[7]+=p1.w;
        }
        *(float4*)&Cp[off]     = make_float4(r[0],r[1],r[2],r[3]);
        *(float4*)&Cp[off + 4] = make_float4(r[4],r[5],r[6],r[7]);
    }
}

// ---------------- forward rFFT (DFT matmul, FFMA2): h rows -> g_A [bc][k][m132] ---------
__global__ __launch_bounds__(160) void k_fft_fwd(const float* __restrict__ h,
                                                 float2* __restrict__ out){
    extern __shared__ u64 sh[];          // [32][256] duplicated values
    int row0 = blockIdx.x*32, t = threadIdx.x;
    for (int i = t*4; i < 32*NLON; i += 160*4){
        float4 v = *(const float4*)&h[(size_t)row0*NLON + i];
        sh[i+0]=dup2f(v.x); sh[i+1]=dup2f(v.y); sh[i+2]=dup2f(v.z); sh[i+3]=dup2f(v.w);
    }
    __syncthreads();
    if (t < MP){
        u64 acc[32];
        #pragma unroll
        for (int r=0;r<32;r++) acc[r]=0ull;
        const u64* tb = (const u64*)(g_dft + (size_t)t*NLON);
        for (int n2=0;n2<NLON/2;n2++){
            ulonglong2 c = *(const ulonglong2*)&tb[n2*2];
            #pragma unroll
            for (int r=0;r<32;r++){
                ulonglong2 v = *(ulonglong2*)&sh[r*NLON + n2*2];
                fma2(acc[r], v.x, c.x);
                fma2(acc[r], v.y, c.y);
            }
        }
        #pragma unroll
        for (int r=0;r<32;r++)
            out[(size_t)(row0+r)*MP + t] = up2(acc[r]);
    }
}

// ---------------- inverse rFFT + gelu + residual: g_B [bc][k][m132] -> h -----------------
__global__ __launch_bounds__(256) void k_fft_inv(const float2* __restrict__ in,
                                                 float* h){
    __shared__ float2 sv[32][MP];
    int row0 = blockIdx.x*32, t = threadIdx.x;
    for (int i = t; i < 32*MP; i += 256){
        int r = i / MP, m = i - r*MP;
        sv[r][m] = in[(size_t)(row0+r)*MP + m];
    }
    __syncthreads();
    u64 acc[32];
    #pragma unroll
    for (int r=0;r<32;r++) acc[r]=0ull;
    for (int m2=0;m2<MP/2;m2++){
        u64 c0 = *(const u64*)&g_idt[(size_t)(2*m2  )*NLON + t];
        u64 c1 = *(const u64*)&g_idt[(size_t)(2*m2+1)*NLON + t];
        #pragma unroll
        for (int r=0;r<32;r++){
            ulonglong2 v = *(ulonglong2*)&sv[r][2*m2];
            fma2(acc[r], v.x, c0);
            fma2(acc[r], v.y, c1);
        }
    }
    #pragma unroll
    for (int r=0;r<32;r++){
        float2 p = up2(acc[r]);
        float s = p.x + p.y;
        size_t idx = (size_t)(row0+r)*NLON + t;
        h[idx] = gelu_tanh(s) + h[idx];
    }
}

// ---------------- Legendre (fwd & inv share form): out[bc,t,m] = sum_j w[m,j,t]*in[bc,j,m]
__global__ __launch_bounds__(128) void k_legendre(const float2* __restrict__ in,
                                                  float2* __restrict__ out,
                                                  const float* __restrict__ w){
    __shared__ float2 s[8][4][128];
    int bc0 = blockIdx.x*8, m0 = blockIdx.y*4, t = threadIdx.x;
    #pragma unroll
    for (int q=0;q<8;q++){
        int lin = t + q*128;
        int j = lin & 127, r = lin >> 7;
        const float4* src = (const float4*)&in[((size_t)(bc0+r)*NLAT + j)*MP + m0];
        float4 v0 = src[0], v1 = src[1];
        s[r][0][j] = make_float2(v0.x,v0.y);
        s[r][1][j] = make_float2(v0.z,v0.w);
        s[r][2][j] = make_float2(v1.x,v1.y);
        s[r][3][j] = make_float2(v1.z,v1.w);
    }
    __syncthreads();
    u64 acc[8][4];
    #pragma unroll
    for (int r=0;r<8;r++)
        #pragma unroll
        for (int m4=0;m4<4;m4++) acc[r][m4]=0ull;
    for (int j=0;j<NLAT;j++){
        u64 wd[4];
        #pragma unroll
        for (int m4=0;m4<4;m4++)
            wd[m4] = dup2f(w[((size_t)(m0+m4)*NLAT + j)*NLAT + t]);
        #pragma unroll
        for (int r=0;r<8;r++)
            #pragma unroll
            for (int m4=0;m4<4;m4++){
                u64 v = *(const u64*)&s[r][m4][j];
                fma2(acc[r][m4], v, wd[m4]);
            }
    }
    #pragma unroll
    for (int r=0;r<8;r++){
        float2 c0 = up2(acc[r][0]), c1 = up2(acc[r][1]);
        float2 c2 = up2(acc[r][2]), c3 = up2(acc[r][3]);
        float4* dst = (float4*)&out[((size_t)(bc0+r)*NLAT + t)*MP + m0];
        dst[0] = make_float4(c0.x,c0.y,c1.x,c1.y);
        dst[1] = make_float4(c2.x,c2.y,c3.x,c3.y);
    }
}

// ---------------- dhconv: out[b,o,l,m] = sum_i in[b,i,l,m] * W[l,i,o] (complex) ----------
__global__ __launch_bounds__(256) void k_dhconv(const float2* __restrict__ in,
                                                float2* __restrict__ out,
                                                const float2* __restrict__ w){
    __shared__ float2 Av[2][16][32];
    __shared__ float2 Wa[16][64];
    __shared__ float2 Wb[16][64];
    int m0 = blockIdx.x*32, l = blockIdx.y, o0 = blockIdx.z*64;
    int t = threadIdx.x, mm = t & 31, og = t >> 5;
    int m = m0 + mm;
    bool mok = (m < MP);
    u64 acc[2][8];
    #pragma unroll
    for (int b2=0;b2<2;b2++)
        #pragma unroll
        for (int j=0;j<8;j++) acc[b2][j]=0ull;

    for (int i0=0;i0<EMB;i0+=16){
        #pragma unroll
        for (int q=0;q<4;q++){
            int lin = t + q*256;
            int amm = lin & 31, aii = (lin >> 5) & 15, ab = lin >> 9;
            int am = m0 + amm;
            float2 v = make_float2(0.f,0.f);
            if (am < MP)
                v = in[((size_t)(ab*EMB + i0+aii)*NLAT + l)*MP + am];
            Av[ab][aii][amm] = v;
        }
        #pragma unroll
        for (int q=0;q<4;q++){
            int lin = t + q*256;
            int oo = lin & 63, wii = lin >> 6;
            float2 wv = w[((size_t)l*EMB + i0+wii)*EMB + o0 + oo];
            Wa[wii][oo] = wv;
            Wb[wii][oo] = make_float2(-wv.y, wv.x);
        }
        __syncthreads();
        #pragma unroll
        for (int ii=0;ii<16;ii++){
            ulonglong2 wa0 = *(ulonglong2*)&Wa[ii][og*8+0];
            ulonglong2 wa1 = *(ulonglong2*)&Wa[ii][og*8+2];
            ulonglong2 wa2 = *(ulonglong2*)&Wa[ii][og*8+4];
            ulonglong2 wa3 = *(ulonglong2*)&Wa[ii][og*8+6];
            ulonglong2 wb0 = *(ulonglong2*)&Wb[ii][og*8+0];
            ulonglong2 wb1 = *(ulonglong2*)&Wb[ii][og*8+2];
            ulonglong2 wb2 = *(ulonglong2*)&Wb[ii][og*8+4];
            ulonglong2 wb3 = *(ulonglong2*)&Wb[ii][og*8+6];
            u64 wav[8] = {wa0.x,wa0.y,wa1.x,wa1.y,wa2.x,wa2.y,wa3.x,wa3.y};
            u64 wbv[8] = {wb0.x,wb0.y,wb1.x,wb1.y,wb2.x,wb2.y,wb3.x,wb3.y};
            #pragma unroll
            for (int b2=0;b2<2;b2++){
                float2 a = Av[b2][ii][mm];
                u64 ax = dup2f(a.x), ay = dup2f(a.y);
                #pragma unroll
                for (int j=0;j<8;j++){
                    fma2(acc[b2][j], ax, wav[j]);
                    fma2(acc[b2][j], ay, wbv[j]);
                }
            }
        }
        __syncthreads();
    }
    if (mok){
        #pragma unroll
        for (int b2=0;b2<2;b2++)
            #pragma unroll
            for (int j=0;j<8;j++)
                out[((size_t)(b2*EMB + o0 + og*8 + j)*NLAT + l)*MP + m] = up2(acc[b2][j]);
    }
}

// ---------------- launcher ----------------
extern "C" void kernel_launch(void* const* d_in, const int* in_sizes, int n_in,
                              void* d_out, int out_size){
    const float* x       = (const float*)d_in[0];
    const float* w_enc   = (const float*)d_in[1];
    const float* b_enc   = (const float*)d_in[2];
    const float* pos     = (const float*)d_in[3];
    const float* spec_w  = (const float*)d_in[4];
    const float* w1      = (const float*)d_in[5];
    const float* b1      = (const float*)d_in[6];
    const float* w2      = (const float*)d_in[7];
    const float* b2      = (const float*)d_in[8];
    const float* w_dec   = (const float*)d_in[9];
    const float* b_dec   = (const float*)d_in[10];
    const float* sht_wt  = (const float*)d_in[11];
    const float* isht_wt = (const float*)d_in[12];
    float* out = (float*)d_out;

    float *ph, *pt, *pwtT, *piwt;
    float2 *pA, *pB, *pw;
    cudaGetSymbolAddress((void**)&ph,   g_h);
    cudaGetSymbolAddress((void**)&pt,   g_t);
    cudaGetSymbolAddress((void**)&pA,   g_A);
    cudaGetSymbolAddress((void**)&pB,   g_B);
    cudaGetSymbolAddress((void**)&pw,   g_w);
    cudaGetSymbolAddress((void**)&pwtT, g_wtT);
    cudaGetSymbolAddress((void**)&piwt, g_iwt);

    static bool attr_set = false;
    if (!attr_set){
        cudaFuncSetAttribute(k_fft_fwd, cudaFuncAttributeMaxDynamicSharedMemorySize, 65536);
        attr_set = true;
    }

    k_init_tables<<<(MP*NLON + 255)/256, 256>>>();
    k_prep_wt<<<(MP*NLAT*NLAT + 255)/256, 256>>>(sht_wt, isht_wt);
    {
        dim3 g(NLAY*EMB, EMB/32, NLAT/32);
        k_pack_w<<<g, 256>>>((const float2*)spec_w);
    }

    // encoder: h = W_enc x + b_enc + pos
    {
        dim3 g(PSP/128, 2, NB);
        k_sgemm<<<g, 256>>>(w_enc, x, ph, b_enc, pos, EMB, PSP, CINC, 4);
    }

    for (int l=0;l<NLAY;l++){
        k_fft_fwd<<<ROWS/32, 160, 65536>>>(ph, pA);
        {
            dim3 g(NB*EMB/8, MP/4);
            k_legendre<<<g, 128>>>(pA, pB, pwtT);
        }
        {
            dim3 g(5, NLAT, 4);
            k_dhconv<<<g, 256>>>(pB, pA, pw + (size_t)l*NLAT*EMB*EMB);
        }
        {
            dim3 g(NB*EMB/8, MP/4);
            k_legendre<<<g, 128>>>(pA, pB, piwt);
        }
        k_fft_inv<<<ROWS/32, 256>>>(pB, ph);

        {   // MLP1: t = gelu(W1 h + b1)
            dim3 g(PSP/128, HID/128, NB);
            k_sgemm<<<g, 256>>>(w1 + (size_t)l*HID*EMB, ph, pt,
                                b1 + (size_t)l*HID, nullptr, HID, PSP, EMB, 1);
        }
        {   // MLP2: h = W2 t + b2 + h
            dim3 g(PSP/128, EMB/128, NB);
            k_sgemm<<<g, 256>>>(w2 + (size_t)l*EMB*HID, pt, ph,
                                b2 + (size_t)l*EMB, ph, EMB, PSP, HID, 2);
        }
    }

    // decoder
    {
        dim3 g(PSP/128, 1, NB);
        k_sgemm<<<g, 256>>>(w_dec, ph, out, b_dec, nullptr, COUTC, PSP, EMB, 0);
    }
}